// round 13
// baseline (speedup 1.0000x reference)
#include <cuda_runtime.h>
#include <cuda_bf16.h>

// R1 configuration (certified 67.55us) with ONE change: __stwt write-through
// stores instead of __stcs — testing whether skipping L2 line allocation for
// the 453MB write-once stream relieves the LTS and lifts DRAM throughput.

#define BB 64
#define TT 288
#define VV 24
#define DD 256
// TOD 128 | DOW 32 | DOM 32 | DOY 64

__global__ __launch_bounds__(256, 8) void input_embedding_kernel(
    const float* __restrict__ features,     // (B,T,V)
    const int*   __restrict__ bar_in_day,   // (B,T)
    const int*   __restrict__ day_of_week,  // (B,)
    const int*   __restrict__ day_of_month, // (B,)
    const int*   __restrict__ day_of_year,  // (B,)
    const float4* __restrict__ W,           // (V,D) as float4
    const float4* __restrict__ bias,        // (V,D) as float4
    const float* __restrict__ tod_table,    // (288,128)
    const float* __restrict__ dow_table,    // (7,32)
    const float* __restrict__ dom_table,    // (32,32)
    const float* __restrict__ doy_table,    // (367,64)
    float4* __restrict__ out)               // (B,T,V,D) as float4
{
    __shared__ __align__(16) float pos[DD];
    __shared__ float sx[VV];

    const int bt  = blockIdx.x;       // b*T + t
    const int b   = bt / TT;
    const int tid = threadIdx.x;

    // ---- build composite positional vector pos[0..255] in smem ----
    if (tid < 128) {
        const int tod = bar_in_day[bt];
        pos[tid] = tod_table[tod * 128 + tid];
    } else if (tid < 160) {
        pos[tid] = dow_table[day_of_week[b] * 32 + (tid - 128)];
    } else if (tid < 192) {
        pos[tid] = dom_table[day_of_month[b] * 32 + (tid - 160)];
    } else {
        pos[tid] = doy_table[day_of_year[b] * 64 + (tid - 192)];
    }
    if (tid < VV) sx[tid] = features[bt * VV + tid];
    __syncthreads();

    const float4* __restrict__ pos4 = reinterpret_cast<const float4*>(pos);
    float4* __restrict__ outb = out + (size_t)bt * (VV * DD / 4);

    // 24 rows of 64 float4 = 1536 float4 per block; 6 per thread.
    #pragma unroll
    for (int k = 0; k < 6; k++) {
        const int p  = tid + k * 256;   // 0..1535
        const int v  = p >> 6;          // uniform across each warp
        const int d4 = p & 63;
        const float  x  = sx[v];
        const float4 w  = W[v * 64 + d4];
        const float4 bv = bias[v * 64 + d4];
        const float4 pp = pos4[d4];
        float4 o;
        o.x = fmaf(x, w.x, bv.x) + pp.x;
        o.y = fmaf(x, w.y, bv.y) + pp.y;
        o.z = fmaf(x, w.z, bv.z) + pp.z;
        o.w = fmaf(x, w.w, bv.w) + pp.w;
        __stwt(&outb[p], o);            // write-through: no L2 line allocation
    }
}

extern "C" void kernel_launch(void* const* d_in, const int* in_sizes, int n_in,
                              void* d_out, int out_size) {
    const float* features     = (const float*)d_in[0];
    const int*   bar_in_day   = (const int*)d_in[1];
    const int*   day_of_week  = (const int*)d_in[2];
    const int*   day_of_month = (const int*)d_in[3];
    const int*   day_of_year  = (const int*)d_in[4];
    const float4* W           = (const float4*)d_in[5];
    const float4* bias        = (const float4*)d_in[6];
    const float* tod_table    = (const float*)d_in[7];
    const float* dow_table    = (const float*)d_in[8];
    const float* dom_table    = (const float*)d_in[9];
    const float* doy_table    = (const float*)d_in[10];
    float4* out = (float4*)d_out;

    input_embedding_kernel<<<BB * TT, 256>>>(
        features, bar_in_day, day_of_week, day_of_month, day_of_year,
        W, bias, tod_table, dow_table, dom_table, doy_table, out);
}

// round 14
// speedup vs baseline: 1.0606x; 1.0606x over previous
#include <cuda_runtime.h>
#include <cuda_bf16.h>

// ============================ FINAL KERNEL ============================
// Certified across R1/R7/R10/R12 at 67.55us (453MB output @ ~6.7TB/s,
// ~84% of HBM spec — the practical write-only DRAM ceiling on sm_100a).
//
// Design invariants (each violation measured and regressed):
//   - one 256-thread CTA per (b,t), 18432 CTAs: cross-CTA overlap hides
//     pos-gather latency (in-loop barriers: R11 +97%; persistent: R2 +12%)
//   - 64 warps/SM (48: R3 +9%; 16: R2 +12%)
//   - per-iteration sx/W/bias/pos loads interleave independent work between
//     stores (hoisting: R5 +6%; register-caching: R9 +48%)
//   - __stcs 128-bit streaming stores (.wb: R4 +3%; .wt: R13 +6%;
//     256-bit st.v8: R6 +9%)
// ======================================================================

#define BB 64
#define TT 288
#define VV 24
#define DD 256
// TOD 128 | DOW 32 | DOM 32 | DOY 64

__global__ __launch_bounds__(256, 8) void input_embedding_kernel(
    const float* __restrict__ features,     // (B,T,V)
    const int*   __restrict__ bar_in_day,   // (B,T)
    const int*   __restrict__ day_of_week,  // (B,)
    const int*   __restrict__ day_of_month, // (B,)
    const int*   __restrict__ day_of_year,  // (B,)
    const float4* __restrict__ W,           // (V,D) as float4
    const float4* __restrict__ bias,        // (V,D) as float4
    const float* __restrict__ tod_table,    // (288,128)
    const float* __restrict__ dow_table,    // (7,32)
    const float* __restrict__ dom_table,    // (32,32)
    const float* __restrict__ doy_table,    // (367,64)
    float4* __restrict__ out)               // (B,T,V,D) as float4
{
    __shared__ __align__(16) float pos[DD];
    __shared__ float sx[VV];

    const int bt  = blockIdx.x;       // b*T + t
    const int b   = bt / TT;
    const int tid = threadIdx.x;

    // ---- build composite positional vector pos[0..255] in smem ----
    if (tid < 128) {
        const int tod = bar_in_day[bt];
        pos[tid] = tod_table[tod * 128 + tid];
    } else if (tid < 160) {
        pos[tid] = dow_table[day_of_week[b] * 32 + (tid - 128)];
    } else if (tid < 192) {
        pos[tid] = dom_table[day_of_month[b] * 32 + (tid - 160)];
    } else {
        pos[tid] = doy_table[day_of_year[b] * 64 + (tid - 192)];
    }
    if (tid < VV) sx[tid] = features[bt * VV + tid];
    __syncthreads();

    const float4* __restrict__ pos4 = reinterpret_cast<const float4*>(pos);
    float4* __restrict__ outb = out + (size_t)bt * (VV * DD / 4);

    // 24 rows of 64 float4 = 1536 float4 per block; 6 per thread.
    #pragma unroll
    for (int k = 0; k < 6; k++) {
        const int p  = tid + k * 256;   // 0..1535
        const int v  = p >> 6;          // uniform across each warp
        const int d4 = p & 63;
        const float  x  = sx[v];
        const float4 w  = W[v * 64 + d4];
        const float4 bv = bias[v * 64 + d4];
        const float4 pp = pos4[d4];
        float4 o;
        o.x = fmaf(x, w.x, bv.x) + pp.x;
        o.y = fmaf(x, w.y, bv.y) + pp.y;
        o.z = fmaf(x, w.z, bv.z) + pp.z;
        o.w = fmaf(x, w.w, bv.w) + pp.w;
        __stcs(&outb[p], o);            // streaming store: keep output out of L2
    }
}

extern "C" void kernel_launch(void* const* d_in, const int* in_sizes, int n_in,
                              void* d_out, int out_size) {
    const float* features     = (const float*)d_in[0];
    const int*   bar_in_day   = (const int*)d_in[1];
    const int*   day_of_week  = (const int*)d_in[2];
    const int*   day_of_month = (const int*)d_in[3];
    const int*   day_of_year  = (const int*)d_in[4];
    const float4* W           = (const float4*)d_in[5];
    const float4* bias        = (const float4*)d_in[6];
    const float* tod_table    = (const float*)d_in[7];
    const float* dow_table    = (const float*)d_in[8];
    const float* dom_table    = (const float*)d_in[9];
    const float* doy_table    = (const float*)d_in[10];
    float4* out = (float4*)d_out;

    input_embedding_kernel<<<BB * TT, 256>>>(
        features, bar_in_day, day_of_week, day_of_month, day_of_year,
        W, bias, tod_table, dow_table, dom_table, doy_table, out);
}